// round 3
// baseline (speedup 1.0000x reference)
#include <cuda_runtime.h>
#include <cuda_bf16.h>
#include <cstdint>
#include <cstddef>

#define DEV_INLINE __device__ __forceinline__

// ---------------- problem constants (fixed shapes) ----------------
constexpr int N_ROWS = 4096;
constexpr int DIM    = 512;
constexpr int NCLS   = 50000;
constexpr float S_SCALE    = 30.0f;
constexpr float MARGIN_COS = 0.9210609940028851f;  // cos(0.4)
constexpr float MARGIN_SIN = 0.3894183423086505f;  // sin(0.4)

// ---------------- GEMM tiling ----------------
constexpr int BM = 128;
constexpr int BN = 128;
constexpr int BK = 64;                 // 64 bf16 = 128B rows (SW128 atom)
constexpr int NKI = DIM / BK;          // 8 k-iterations
constexpr int MTILES = N_ROWS / BM;                  // 32
constexpr int NTILES = (NCLS + BN - 1) / BN;         // 391 (last masked)

constexpr uint32_t ABUF = BM * 128;    // 16384 bytes per stage
constexpr uint32_t BBUF = BN * 128;    // 16384 bytes per stage
constexpr uint32_t SMEM_EXCL = 2 * ABUF + 2 * BBUF;          // 65536
constexpr uint32_t SMEM_TG   = SMEM_EXCL + BM * 4;           // 66048
constexpr uint32_t SMEM_TOTAL = SMEM_TG + BM * 4;            // 66560

// ---------------- device scratch (allocation-free rule) ----------------
__device__ __nv_bfloat16 g_xbf[(size_t)N_ROWS * DIM];   // normalized x, bf16
__device__ __nv_bfloat16 g_wbf[(size_t)NCLS * DIM];     // W, bf16 (51MB, mostly L2)
__device__ float g_excl[N_ROWS];
__device__ float g_tgt[N_ROWS];

// ---------------- helpers ----------------
DEV_INLINE uint32_t smem_u32(const void* p) { return (uint32_t)__cvta_generic_to_shared(p); }
DEV_INLINE uint32_t swz(uint32_t o) { return o ^ ((o >> 3) & 0x70); }

DEV_INLINE void cp16(uint32_t dst, const void* src) {
    asm volatile("cp.async.cg.shared.global [%0], [%1], 16;" :: "r"(dst), "l"(src));
}

DEV_INLINE void ldm_x4(uint32_t& r0, uint32_t& r1, uint32_t& r2, uint32_t& r3,
                       uint32_t addr) {
    asm volatile("ldmatrix.sync.aligned.m8n8.x4.shared.b16 {%0,%1,%2,%3}, [%4];"
                 : "=r"(r0), "=r"(r1), "=r"(r2), "=r"(r3) : "r"(addr));
}

DEV_INLINE void mma_bf16(float* d, const uint32_t* a, uint32_t b0, uint32_t b1) {
    asm volatile(
        "mma.sync.aligned.m16n8k16.row.col.f32.bf16.bf16.f32 "
        "{%0,%1,%2,%3}, {%4,%5,%6,%7}, {%8,%9}, {%0,%1,%2,%3};"
        : "+f"(d[0]), "+f"(d[1]), "+f"(d[2]), "+f"(d[3])
        : "r"(a[0]), "r"(a[1]), "r"(a[2]), "r"(a[3]), "r"(b0), "r"(b1));
}

// ---------------- kernel 1: W fp32 -> bf16 ----------------
__global__ void conv_w_kernel(const float* __restrict__ W) {
    size_t i = ((size_t)blockIdx.x * blockDim.x + threadIdx.x) * 4;
    float4 v = *reinterpret_cast<const float4*>(W + i);
    *reinterpret_cast<__nv_bfloat162*>(g_wbf + i)     = __floats2bfloat162_rn(v.x, v.y);
    *reinterpret_cast<__nv_bfloat162*>(g_wbf + i + 2) = __floats2bfloat162_rn(v.z, v.w);
}

// ---------------- kernel 2: normalize x rows -> bf16 (+ zero excl) ----------------
__global__ void prep_x_kernel(const float* __restrict__ x) {
    int row = blockIdx.x * 8 + (threadIdx.x >> 5);
    int lid = threadIdx.x & 31;
    const float* xr = x + (size_t)row * DIM;
    float s = 0.0f;
#pragma unroll
    for (int j = 0; j < 16; j++) { float v = xr[lid + j * 32]; s += v * v; }
#pragma unroll
    for (int o = 16; o; o >>= 1) s += __shfl_xor_sync(0xFFFFFFFFu, s, o);
    float rn = rsqrtf(s);
    __nv_bfloat16* outr = g_xbf + (size_t)row * DIM;
#pragma unroll
    for (int j = 0; j < 16; j++) {
        int d = lid + j * 32;
        outr[d] = __float2bfloat16(xr[d] * rn);
    }
    if (lid == 0) g_excl[row] = 0.0f;   // must re-zero on every graph replay
}

// ---------------- kernel 3: HMMA GEMM + fused arcface epilogue ----------------
__global__ void __launch_bounds__(256, 2)
arc_gemm_kernel(const int* __restrict__ target) {
    extern __shared__ char smem[];
    const uint32_t sb = smem_u32(smem);
    const uint32_t sA = sb;
    const uint32_t sB = sb + 2 * ABUF;
    float* s_excl = reinterpret_cast<float*>(smem + SMEM_EXCL);
    int*   s_tg   = reinterpret_cast<int*>(smem + SMEM_TG);

    const int tid = threadIdx.x;
    const int lid = tid & 31;
    const int wid = tid >> 5;
    const int wm  = wid & 1;          // 0..1  (m direction, 64 rows each)
    const int wn  = wid >> 1;         // 0..3  (n direction, 32 cols each)
    const int rbase = blockIdx.x * BM;
    const int cbase = blockIdx.y * BN;

    if (tid < BM) {
        s_excl[tid] = 0.0f;
        s_tg[tid]   = target[rbase + tid];
    }

    // per-thread cp.async source/dest prep: 1024 chunks of 16B per tile, 4 per thread
    // chunk = tid + i*256 ; row = chunk>>3 ; kb = chunk&7
    const int c_row = tid >> 3;              // base row for i=0 (rows advance by 32)
    const int c_kb  = tid & 7;

    // ldmatrix address components (within-buffer byte offsets, swizzled at use)
    const uint32_t a_row = wm * 64 + (lid & 15);
    const uint32_t a_koff = (lid >> 4) * 16;
    const uint32_t b_row = wn * 32 + (lid & 7) + ((lid >> 4) & 1) * 8;
    const uint32_t b_koff = ((lid >> 3) & 1) * 16;

    float acc[4][4][4];
#pragma unroll
    for (int mt = 0; mt < 4; mt++)
#pragma unroll
        for (int nt = 0; nt < 4; nt++)
#pragma unroll
            for (int j = 0; j < 4; j++) acc[mt][nt][j] = 0.0f;

    // ---- prefetch k=0 into stage 0 ----
    {
        const __nv_bfloat16* xs = g_xbf + (size_t)rbase * DIM;
#pragma unroll
        for (int i = 0; i < 4; i++) {
            int row = c_row + i * 32;
            cp16(sA + swz(row * 128 + c_kb * 16), xs + (size_t)row * DIM + c_kb * 8);
        }
#pragma unroll
        for (int i = 0; i < 4; i++) {
            int row = c_row + i * 32;
            int c = cbase + row; c = (c < NCLS) ? c : (NCLS - 1);
            cp16(sB + swz(row * 128 + c_kb * 16), g_wbf + (size_t)c * DIM + c_kb * 8);
        }
    }
    asm volatile("cp.async.commit_group;" ::: "memory");

    for (int k = 0; k < NKI; k++) {
        const uint32_t buf = (k & 1) ? 16384u : 0u;
        asm volatile("cp.async.wait_group 0;" ::: "memory");
        __syncthreads();

        if (k + 1 < NKI) {
            const uint32_t nbuf = buf ^ 16384u;
            const int k0 = (k + 1) * BK;
            const __nv_bfloat16* xs = g_xbf + (size_t)rbase * DIM + k0;
#pragma unroll
            for (int i = 0; i < 4; i++) {
                int row = c_row + i * 32;
                cp16(sA + nbuf + swz(row * 128 + c_kb * 16),
                     xs + (size_t)row * DIM + c_kb * 8);
            }
            const __nv_bfloat16* ws = g_wbf + k0;
#pragma unroll
            for (int i = 0; i < 4; i++) {
                int row = c_row + i * 32;
                int c = cbase + row; c = (c < NCLS) ? c : (NCLS - 1);
                cp16(sB + nbuf + swz(row * 128 + c_kb * 16), ws + (size_t)c * DIM + c_kb * 8);
            }
            asm volatile("cp.async.commit_group;" ::: "memory");
        }

        // ---- compute BK=64 as 4 k-steps of 16 ----
#pragma unroll
        for (int kk = 0; kk < 4; kk++) {
            uint32_t a[4][4];
#pragma unroll
            for (int mt = 0; mt < 4; mt++) {
                uint32_t addr = sA + buf +
                    swz((a_row + mt * 16) * 128 + kk * 32 + a_koff);
                ldm_x4(a[mt][0], a[mt][1], a[mt][2], a[mt][3], addr);
            }
            uint32_t b[4][2];
#pragma unroll
            for (int np = 0; np < 2; np++) {
                uint32_t r0, r1, r2, r3;
                uint32_t addr = sB + buf +
                    swz((b_row + np * 16) * 128 + kk * 32 + b_koff);
                ldm_x4(r0, r1, r2, r3, addr);
                b[np * 2][0] = r0; b[np * 2][1] = r1;
                b[np * 2 + 1][0] = r2; b[np * 2 + 1][1] = r3;
            }
#pragma unroll
            for (int mt = 0; mt < 4; mt++)
#pragma unroll
                for (int nt = 0; nt < 4; nt++)
                    mma_bf16(acc[mt][nt], a[mt], b[nt][0], b[nt][1]);
        }
    }
    __syncthreads();

    // ---- fused epilogue from accumulator registers ----
    // c-frag: d0=(r,c0) d1=(r,c0+1) d2=(r+8,c0) d3=(r+8,c0+1); r=lid>>2, c0=2*(lid&3)
#pragma unroll
    for (int mt = 0; mt < 4; mt++) {
#pragma unroll
        for (int h = 0; h < 2; h++) {
            int rloc = wm * 64 + mt * 16 + (lid >> 2) + h * 8;
            int tg = s_tg[rloc];
            float s = 0.0f;
#pragma unroll
            for (int nt = 0; nt < 4; nt++) {
#pragma unroll
                for (int j = 0; j < 2; j++) {
                    int c = cbase + wn * 32 + nt * 8 + 2 * (lid & 3) + j;
                    float v = acc[mt][nt][h * 2 + j];
                    if (c < NCLS) {
                        if (c == tg) g_tgt[rbase + rloc] = v;
                        else         s += __expf(S_SCALE * v);
                    }
                }
            }
            // quad reduce (lanes 4t..4t+3 share rloc)
            s += __shfl_xor_sync(0xFFFFFFFFu, s, 1);
            s += __shfl_xor_sync(0xFFFFFFFFu, s, 2);
            if ((lid & 3) == 0) atomicAdd(&s_excl[rloc], s);
        }
    }
    __syncthreads();
    if (tid < BM) atomicAdd(&g_excl[rbase + tid], s_excl[tid]);
}

// ---------------- kernel 4: final reduction ----------------
__global__ void finalize_kernel(float* __restrict__ out) {
    __shared__ float red[8];
    int tid = threadIdx.x;
    float s = 0.0f;
    for (int i = tid; i < N_ROWS; i += 256) {
        float t = g_tgt[i];
        t = fminf(fmaxf(t, -1.0f + 1e-7f), 1.0f - 1e-7f);
        float num = S_SCALE * (t * MARGIN_COS - sqrtf(fmaxf(1.0f - t * t, 0.0f)) * MARGIN_SIN);
        float den = expf(num) + g_excl[i];
        s += num - logf(den);
    }
#pragma unroll
    for (int o = 16; o; o >>= 1) s += __shfl_xor_sync(0xFFFFFFFFu, s, o);
    if ((tid & 31) == 0) red[tid >> 5] = s;
    __syncthreads();
    if (tid < 8) {
        float v = red[tid];
#pragma unroll
        for (int o = 4; o; o >>= 1) v += __shfl_xor_sync(0xFFu, v, o);
        if (tid == 0) out[0] = -v / (float)N_ROWS;
    }
}

// ---------------- launch ----------------
extern "C" void kernel_launch(void* const* d_in, const int* in_sizes, int n_in,
                              void* d_out, int out_size) {
    const float* x      = (const float*)d_in[0];
    const float* W      = (const float*)d_in[1];
    const int*   target = (const int*)d_in[2];
    float*       out    = (float*)d_out;

    cudaFuncSetAttribute(arc_gemm_kernel,
                         cudaFuncAttributeMaxDynamicSharedMemorySize, SMEM_TOTAL);

    conv_w_kernel<<<(int)(((size_t)NCLS * DIM) / 1024), 256>>>(W);
    prep_x_kernel<<<N_ROWS / 8, 256>>>(x);
    arc_gemm_kernel<<<dim3(MTILES, NTILES), 256, SMEM_TOTAL>>>(target);
    finalize_kernel<<<1, 256>>>(out);
}